// round 7
// baseline (speedup 1.0000x reference)
#include <cuda_runtime.h>
#include <cuda_fp16.h>
#include <cstdint>

// Problem constants
#define MROWS  131072      // N*H*W*L
#define CDIM   256
#define NBATCH 512
#define HEADS  8
#define HD     32
#define LSEQ   256
// QK scale folded with log2(e): exp(s/sqrt(32)) = 2^(s * QEXP_SCALE)
#define QEXP_SCALE (0.17677669529663689f * 1.4426950408889634f)

// -------- scratch (device globals) --------
__device__ __half g_X[(size_t)MROWS * CDIM];
__device__ __half g_Q[(size_t)NBATCH * HEADS * LSEQ * HD];
__device__ __half g_K[(size_t)NBATCH * HEADS * LSEQ * HD];
__device__ __half g_V[(size_t)NBATCH * HEADS * LSEQ * HD];
__device__ __half g_O[(size_t)MROWS * CDIM];
__device__ __half g_Wt[4 * CDIM * CDIM];   // [w][n][k] = W_w[k][n] as half

// -------- helpers --------
__device__ __forceinline__ void mma16(float c[4], const unsigned a[4],
                                      unsigned b0, unsigned b1) {
    asm volatile(
        "mma.sync.aligned.m16n8k16.row.col.f32.f16.f16.f32 "
        "{%0,%1,%2,%3}, {%4,%5,%6,%7}, {%8,%9}, {%0,%1,%2,%3};"
        : "+f"(c[0]), "+f"(c[1]), "+f"(c[2]), "+f"(c[3])
        : "r"(a[0]), "r"(a[1]), "r"(a[2]), "r"(a[3]), "r"(b0), "r"(b1));
}
__device__ __forceinline__ unsigned pack2(float lo, float hi) {
    __half2 h = __floats2half2_rn(lo, hi);
    return *reinterpret_cast<unsigned*>(&h);
}
__device__ __forceinline__ unsigned ldu32(const __half* p) {
    return *reinterpret_cast<const unsigned*>(p);
}
__device__ __forceinline__ unsigned ex2h2(unsigned x) {
    unsigned r;
    asm("ex2.approx.f16x2 %0, %1;" : "=r"(r) : "r"(x));
    return r;
}
__device__ __forceinline__ uint32_t smem_u32(const void* p) {
    uint32_t a;
    asm("{ .reg .u64 t; cvta.to.shared.u64 t, %1; cvt.u32.u64 %0, t; }"
        : "=r"(a) : "l"(p));
    return a;
}
__device__ __forceinline__ void ldsm4(unsigned& r0, unsigned& r1,
                                      unsigned& r2, unsigned& r3, uint32_t a) {
    asm volatile("ldmatrix.sync.aligned.m8n8.x4.shared.b16 {%0,%1,%2,%3}, [%4];"
                 : "=r"(r0), "=r"(r1), "=r"(r2), "=r"(r3) : "r"(a));
}
__device__ __forceinline__ void cpasync16(uint32_t dst, const void* src) {
    asm volatile("cp.async.cg.shared.global [%0], [%1], 16;"
                 :: "r"(dst), "l"(src));
}

// ============================================================================
// pre-kernels: convert X to half; build Wt[w][n][k] = W_w[k][n] half
// ============================================================================
__global__ __launch_bounds__(256) void convert_x_kernel(
    const float* __restrict__ x, __half* __restrict__ xh)
{
    const size_t i = ((size_t)blockIdx.x * 256 + threadIdx.x) * 8;
    const float4 a = *(const float4*)(x + i);
    const float4 b = *(const float4*)(x + i + 4);
    uint4 v;
    v.x = pack2(a.x, a.y); v.y = pack2(a.z, a.w);
    v.z = pack2(b.x, b.y); v.w = pack2(b.z, b.w);
    *(uint4*)(xh + i) = v;
}

__global__ __launch_bounds__(256) void transpose_w_kernel(
    const float* __restrict__ W0, const float* __restrict__ W1,
    const float* __restrict__ W2, const float* __restrict__ W3,
    __half* __restrict__ Wt)
{
    __shared__ float tile[64][65];
    const int w  = blockIdx.z;
    const int k0 = blockIdx.x * 64;
    const int n0 = blockIdx.y * 64;
    const float* W = w == 0 ? W0 : (w == 1 ? W1 : (w == 2 ? W2 : W3));
    const int t = threadIdx.x;
    for (int i = t; i < 4096; i += 256) {
        const int r = i >> 6, c = i & 63;
        tile[c][r] = W[(k0 + r) * CDIM + n0 + c];
    }
    __syncthreads();
    for (int i = t; i < 4096; i += 256) {
        const int r = i >> 6, c = i & 63;
        Wt[(size_t)w * CDIM * CDIM + (n0 + r) * CDIM + k0 + c] = __float2half(tile[r][c]);
    }
}

// ============================================================================
// half GEMM (round-5 design, unchanged): cp.async double-buffered, ldmatrix,
// BM=128 BN=128 BK=64, 2 CTA/SM. MODE 0 Q-output pre-scaled by QEXP_SCALE.
// ============================================================================
#define GST 72
#define XS_HALFS (128 * GST)
#define GEMM_SMEM_BYTES (4 * XS_HALFS * 2)

template <int MODE>
__global__ __launch_bounds__(256, 2) void gemm2_kernel(
    const __half* __restrict__ X, const __half* __restrict__ Wt4,
    const float* __restrict__ b0p, const float* __restrict__ b1p,
    const float* __restrict__ b2p,
    void* __restrict__ o0, void* __restrict__ o1, void* __restrict__ o2)
{
    extern __shared__ __half smh[];
    const uint32_t sb = smem_u32(smh);

    const int t    = threadIdx.x;
    const int lane = t & 31;
    const int wid  = t >> 5;
    const int g    = lane >> 2;
    const int tg   = lane & 3;

    int widx = 0, nx = blockIdx.x;
    if (MODE == 0) { widx = nx >> 1; nx &= 1; }
    const int  n0 = nx * 128;
    const long m0 = (long)blockIdx.y * 128;
    const __half* Wt   = Wt4 + (size_t)widx * CDIM * CDIM;
    const float*  bias = widx == 0 ? b0p : (widx == 1 ? b1p : b2p);
    const float   osc  = (MODE == 0 && widx == 0) ? QEXP_SCALE : 1.0f;

    const int sr  = t >> 3;
    const int sc8 = (t & 7) * 8;

    auto issue = [&](int kb, int buf) {
        const __half* xs = X  + ((m0 + sr) << 8) + kb * 64 + sc8;
        const __half* ws = Wt + ((n0 + sr) << 8) + kb * 64 + sc8;
        const uint32_t xd = sb + (uint32_t)(buf * XS_HALFS + sr * GST + sc8) * 2;
        const uint32_t wd = sb + (uint32_t)((2 + buf) * XS_HALFS + sr * GST + sc8) * 2;
#pragma unroll
        for (int i = 0; i < 4; i++) {
            cpasync16(xd + i * 32 * GST * 2, xs + (i << 13));
            cpasync16(wd + i * 32 * GST * 2, ws + (i << 13));
        }
    };

    float acc[4][4][4] = {};

    const int m0w = (wid & 1) * 64;
    const int n0w = (wid >> 1) * 32;
    const int rr  = lane & 7;
    const int blk = lane >> 3;
    const int arow = m0w + (blk & 1) * 8 + rr;
    const int acol = (blk & 2) * 4;
    const int brow = n0w + ((blk & 2) ? 8 : 0) + rr;
    const int bcol = (blk & 1) * 8;

    issue(0, 0);
    asm volatile("cp.async.commit_group;");

#pragma unroll 1
    for (int kb = 0; kb < 4; kb++) {
        if (kb < 3) {
            issue(kb + 1, (kb + 1) & 1);
            asm volatile("cp.async.commit_group;");
            asm volatile("cp.async.wait_group 1;");
        } else {
            asm volatile("cp.async.wait_group 0;");
        }
        __syncthreads();

        const int buf = kb & 1;
        const uint32_t xbase = sb + (uint32_t)(buf * XS_HALFS) * 2;
        const uint32_t bbase = sb + (uint32_t)((2 + buf) * XS_HALFS) * 2;

#pragma unroll
        for (int kt = 0; kt < 4; kt++) {
            unsigned br[2][4];
#pragma unroll
            for (int nt2 = 0; nt2 < 2; nt2++)
                ldsm4(br[nt2][0], br[nt2][1], br[nt2][2], br[nt2][3],
                      bbase + (uint32_t)((brow + nt2 * 16) * GST + kt * 16 + bcol) * 2);
            unsigned ar[4][4];
#pragma unroll
            for (int mt = 0; mt < 4; mt++)
                ldsm4(ar[mt][0], ar[mt][1], ar[mt][2], ar[mt][3],
                      xbase + (uint32_t)((arow + mt * 16) * GST + kt * 16 + acol) * 2);
#pragma unroll
            for (int mt = 0; mt < 4; mt++) {
#pragma unroll
                for (int nt2 = 0; nt2 < 2; nt2++) {
                    mma16(acc[mt][nt2 * 2],     ar[mt], br[nt2][0], br[nt2][1]);
                    mma16(acc[mt][nt2 * 2 + 1], ar[mt], br[nt2][2], br[nt2][3]);
                }
            }
        }
        __syncthreads();
    }

#pragma unroll
    for (int mt = 0; mt < 4; mt++) {
#pragma unroll
        for (int hi = 0; hi < 2; hi++) {
            const long row = m0 + m0w + mt * 16 + hi * 8 + g;
#pragma unroll
            for (int nt = 0; nt < 4; nt++) {
                const int c = n0 + n0w + nt * 8 + 2 * tg;
                const float v0 = (acc[mt][nt][2 * hi]     + bias[c])     * osc;
                const float v1 = (acc[mt][nt][2 * hi + 1] + bias[c + 1]) * osc;
                if (MODE == 0) {
                    const long bb = row >> 8;
                    const int  l  = (int)(row & 255);
                    const int  ah = c >> 5;
                    const int  d  = c & 31;
                    __half* out = (__half*)(widx == 0 ? o0 : (widx == 1 ? o1 : o2));
                    *(unsigned*)(out + (((bb * HEADS + ah) * LSEQ + l) << 5) + d) = pack2(v0, v1);
                } else {
                    float2 v; v.x = v0; v.y = v1;
                    *(float2*)((float*)o0 + row * CDIM + c) = v;
                }
            }
        }
    }
}

// ============================================================================
// fp16 Attention v3:
//  - max-free softmax, Q pre-scaled for exp2
//  - P = ex2.approx.f16x2 directly on packed half2 A-fragments (16 MUFU/chunk)
//  - row sums via ones-row appended to V (d=32): one extra n8 PV tile, no FADDs
//  - K/V fragments via ldmatrix.x4 (conflict-free strides 80B / 528B)
// ============================================================================
__global__ __launch_bounds__(256, 2) void attn_f16_kernel(
    const __half* __restrict__ Q, const __half* __restrict__ K,
    const __half* __restrict__ V, __half* __restrict__ O)
{
    __shared__ __half Ks[LSEQ][40];    // [key][d]
    __shared__ __half Vs[40][264];     // [d][key]; d=32 row is ones, 33-39 zero

    const int t    = threadIdx.x;
    const int lane = t & 31;
    const int warp = t >> 5;
    const int g    = lane >> 2;
    const int tg   = lane & 3;

    const int  bh = blockIdx.x;
    const int  b  = bh >> 3;
    const int  ah = bh & 7;
    const __half* Kg = K + (long)bh * LSEQ * HD;
    const __half* Vg = V + (long)bh * LSEQ * HD;
    const __half* Qw = Q + (long)bh * LSEQ * HD + warp * 32 * HD;

    // ---- stage K ----
    for (int j = t; j < 2048; j += 256) {
        const int r = j >> 3, q = j & 7;
        *(uint2*)&Ks[r][q * 4] = *(const uint2*)(Kg + r * HD + q * 4);
    }
    // ---- stage V transposed ----
    for (int j = t; j < 4096; j += 256) {
        const int key = j >> 4, d2 = j & 15;
        const __half2 v = *(const __half2*)(Vg + key * HD + d2 * 2);
        Vs[2 * d2][key]     = __low2half(v);
        Vs[2 * d2 + 1][key] = __high2half(v);
    }
    // ---- ones row (d=32) and zero rows (33..39) ----
    const unsigned ONE2 = 0x3C003C00u;
    for (int j = t; j < 1056; j += 256) {
        const int r = j / 132, c = j % 132;
        *(unsigned*)&Vs[32 + r][c * 2] = (r == 0) ? ONE2 : 0u;
    }

    // ---- Q A-fragments from gmem ----
    unsigned qa[2][2][4];
#pragma unroll
    for (int kt = 0; kt < 2; kt++)
#pragma unroll
        for (int mt = 0; mt < 2; mt++) {
            const __half* qp = Qw + (mt * 16 + g) * HD + kt * 16 + 2 * tg;
            qa[kt][mt][0] = ldu32(qp);
            qa[kt][mt][1] = ldu32(qp + 8 * HD);
            qa[kt][mt][2] = ldu32(qp + 8);
            qa[kt][mt][3] = ldu32(qp + 8 * HD + 8);
        }
    __syncthreads();

    // ldmatrix lane bases
    const uint32_t kbase = smem_u32(&Ks[lane & 7][(lane >> 3) * 8]);
    const uint32_t vbase = smem_u32(&Vs[lane & 7][(lane >> 3) * 8]);

    float o[2][4][4]  = {};   // d-tiles 0..3
    float o4[2][4]    = {};   // ones tile (row sums land in col 32)

#pragma unroll 1
    for (int jc = 0; jc < 8; jc++) {
        // ---- K fragments: 4x ldmatrix.x4 -> kb[nt] = {b0k0,b1k0,b0k1,b1k1} ----
        unsigned kb[4][4];
#pragma unroll
        for (int nt = 0; nt < 4; nt++)
            ldsm4(kb[nt][0], kb[nt][1], kb[nt][2], kb[nt][3],
                  kbase + (uint32_t)(jc * 32 + nt * 8) * 80);

        // ---- S = Q K^T ----
        float s[2][4][4] = {};
#pragma unroll
        for (int nt = 0; nt < 4; nt++) {
#pragma unroll
            for (int kt = 0; kt < 2; kt++) {
                mma16(s[0][nt], qa[kt][0], kb[nt][2 * kt], kb[nt][2 * kt + 1]);
                mma16(s[1][nt], qa[kt][1], kb[nt][2 * kt], kb[nt][2 * kt + 1]);
            }
        }

        // ---- P = 2^S in half2: pack then ex2.f16x2 (A-fragments directly) ----
        unsigned pa[2][2][4];   // [kt2][mt][reg]
#pragma unroll
        for (int kt2 = 0; kt2 < 2; kt2++)
#pragma unroll
            for (int mt = 0; mt < 2; mt++) {
                pa[kt2][mt][0] = ex2h2(pack2(s[mt][2 * kt2][0],     s[mt][2 * kt2][1]));
                pa[kt2][mt][1] = ex2h2(pack2(s[mt][2 * kt2][2],     s[mt][2 * kt2][3]));
                pa[kt2][mt][2] = ex2h2(pack2(s[mt][2 * kt2 + 1][0], s[mt][2 * kt2 + 1][1]));
                pa[kt2][mt][3] = ex2h2(pack2(s[mt][2 * kt2 + 1][2], s[mt][2 * kt2 + 1][3]));
            }

        // ---- O += P V  (5 d-tiles; tile 4 = ones column -> row sums) ----
#pragma unroll
        for (int dt = 0; dt < 5; dt++) {
            unsigned vb[4];
            ldsm4(vb[0], vb[1], vb[2], vb[3],
                  vbase + (uint32_t)dt * 4224 + (uint32_t)jc * 64);
            float* o0p = (dt < 4) ? o[0][dt] : o4[0];
            float* o1p = (dt < 4) ? o[1][dt] : o4[1];
#pragma unroll
            for (int kt2 = 0; kt2 < 2; kt2++) {
                mma16(o0p, pa[kt2][0], vb[2 * kt2], vb[2 * kt2 + 1]);
                mma16(o1p, pa[kt2][1], vb[2 * kt2], vb[2 * kt2 + 1]);
            }
        }
    }

    // ---- finalize: row sum is o4[mt][2hi] on tg==0 lanes (col 32) ----
#pragma unroll
    for (int mt = 0; mt < 2; mt++) {
#pragma unroll
        for (int hi = 0; hi < 2; hi++) {
            const float sum = __shfl_sync(0xffffffffu, o4[mt][2 * hi], lane & ~3);
            const float inv = __fdividef(1.0f, sum);
            const int l = warp * 32 + mt * 16 + hi * 8 + g;
#pragma unroll
            for (int dt = 0; dt < 4; dt++) {
                const int c = ah * HD + dt * 8 + 2 * tg;
                *(unsigned*)(O + ((long)(b * LSEQ + l)) * CDIM + c) =
                    pack2(o[mt][dt][2 * hi] * inv, o[mt][dt][2 * hi + 1] * inv);
            }
        }
    }
}

// ============================================================================
// launch
// ============================================================================
extern "C" void kernel_launch(void* const* d_in, const int* in_sizes, int n_in,
                              void* d_out, int out_size)
{
    const float* x  = (const float*)d_in[0];
    const float* Wq = (const float*)d_in[1];
    const float* bq = (const float*)d_in[2];
    const float* Wk = (const float*)d_in[3];
    const float* bk = (const float*)d_in[4];
    const float* Wv = (const float*)d_in[5];
    const float* bv = (const float*)d_in[6];
    const float* Wp = (const float*)d_in[7];
    const float* bp = (const float*)d_in[8];

    __half *xh, *qp, *kp, *vp, *op, *wt;
    cudaGetSymbolAddress((void**)&xh, g_X);
    cudaGetSymbolAddress((void**)&qp, g_Q);
    cudaGetSymbolAddress((void**)&kp, g_K);
    cudaGetSymbolAddress((void**)&vp, g_V);
    cudaGetSymbolAddress((void**)&op, g_O);
    cudaGetSymbolAddress((void**)&wt, g_Wt);

    cudaFuncSetAttribute(gemm2_kernel<0>,
                         cudaFuncAttributeMaxDynamicSharedMemorySize, GEMM_SMEM_BYTES);
    cudaFuncSetAttribute(gemm2_kernel<1>,
                         cudaFuncAttributeMaxDynamicSharedMemorySize, GEMM_SMEM_BYTES);

    convert_x_kernel<<<(MROWS * CDIM) / (256 * 8), 256>>>(x, xh);
    transpose_w_kernel<<<dim3(4, 4, 4), 256>>>(Wq, Wk, Wv, Wp, wt);

    dim3 gqkv(6, MROWS / 128);
    gemm2_kernel<0><<<gqkv, 256, GEMM_SMEM_BYTES>>>(
        xh, wt, bq, bk, bv, qp, kp, vp);

    attn_f16_kernel<<<NBATCH * HEADS, 256>>>(qp, kp, vp, op);

    dim3 gp(2, MROWS / 128);
    gemm2_kernel<1><<<gp, 256, GEMM_SMEM_BYTES>>>(
        op, wt + 3 * CDIM * CDIM, bp, bp, bp, d_out, d_out, d_out);
}